// round 2
// baseline (speedup 1.0000x reference)
#include <cuda_runtime.h>

#define OUT_COLS 256
#define SLICE 64
#define NSLICES (OUT_COLS / SLICE)
#define BLOCK_THREADS 512
#define NWARPS (BLOCK_THREADS / 32)
#define ROW_BLOCKS 38   // 4 slices * 38 = 152 CTAs = one wave on GB300 (152 SMs)

// scratch (static __device__ globals: no allocations allowed)
__device__ int2 g_pairs[1 << 20];          // (col, val_bits) per nnz; nnz=524288 fits
__device__ int  g_row_off[(1 << 16) + 2];  // N+1 row segment offsets; N=16384 fits

// Prep: gather f_table[active_idx] into packed pairs, build row offsets from
// the sorted batch_idx (boundary detection + gap fill handles empty rows).
__global__ void prep_kernel(const int* __restrict__ bidx,
                            const int* __restrict__ aidx,
                            const float* __restrict__ vals,
                            const int* __restrict__ ftab,
                            int nnz, int N) {
    int k = blockIdx.x * blockDim.x + threadIdx.x;
    if (k >= nnz) return;
    int col = ftab[aidx[k]];
    g_pairs[k] = make_int2(col, __float_as_int(vals[k]));
    int b = bidx[k];
    int prev = (k == 0) ? -1 : bidx[k - 1];
    for (int r = prev + 1; r <= b; ++r) g_row_off[r] = k;
    if (k == nnz - 1) {
        for (int r = b + 1; r <= N; ++r) g_row_off[r] = nnz;
    }
}

// Main: each CTA owns a 64-wide column slice of W cached in SMEM.
// Each warp owns one output row at a time: stage up to 32 (col,val) pairs to
// SMEM, then broadcast-read them and accumulate val * W_s[col][lane{,+32}].
__global__ __launch_bounds__(BLOCK_THREADS, 1)
void spmm_kernel(const float* __restrict__ W, float* __restrict__ out,
                 int N, int inter_dim) {
    extern __shared__ float smem[];
    float* Ws = smem;                                   // [inter_dim][SLICE]
    int2* stage = (int2*)(smem + inter_dim * SLICE);    // [NWARPS][32]

    int slice = blockIdx.x % NSLICES;
    int rb    = blockIdx.x / NSLICES;
    int nrb   = gridDim.x / NSLICES;

    int warp = threadIdx.x >> 5;
    int lane = threadIdx.x & 31;
    int2* mystage = stage + warp * 32;

    int col0 = slice * SLICE;

    // Load this CTA's weight slice into SMEM (float4, coalesced).
    int nvec = inter_dim * (SLICE / 4);
    for (int i = threadIdx.x; i < nvec; i += BLOCK_THREADS) {
        int r  = i >> 4;        // / (SLICE/4) == 16
        int c4 = i & 15;
        float4 v = *(const float4*)(W + (size_t)r * OUT_COLS + col0 + c4 * 4);
        *(float4*)(Ws + r * SLICE + c4 * 4) = v;
    }
    __syncthreads();

    for (int row = rb * NWARPS + warp; row < N; row += nrb * NWARPS) {
        int s = g_row_off[row];
        int e = g_row_off[row + 1];
        float acc0 = 0.f, acc1 = 0.f;
        for (int base = s; base < e; base += 32) {
            int cnt = min(32, e - base);
            if (lane < cnt) mystage[lane] = g_pairs[base + lane];
            __syncwarp();
#pragma unroll 4
            for (int j = 0; j < cnt; ++j) {
                int2 p = mystage[j];                    // uniform broadcast LDS.64
                float v = __int_as_float(p.y);
                const float* wr = Ws + p.x * SLICE;     // conflict-free LDS.32
                acc0 = fmaf(v, wr[lane], acc0);
                acc1 = fmaf(v, wr[lane + 32], acc1);
            }
            __syncwarp();
        }
        float* orow = out + (size_t)row * OUT_COLS + col0;
        orow[lane]      = acc0;     // writes every row (zeros for empty rows)
        orow[lane + 32] = acc1;
    }
}

extern "C" void kernel_launch(void* const* d_in, const int* in_sizes, int n_in,
                              void* d_out, int out_size) {
    const int*   bidx = (const int*)d_in[0];
    const int*   aidx = (const int*)d_in[1];
    const float* vals = (const float*)d_in[2];
    const int*   ftab = (const int*)d_in[3];
    const float* W    = (const float*)d_in[4];

    int nnz       = in_sizes[0];
    int inter_dim = in_sizes[4] / OUT_COLS;   // 768
    int N         = out_size / OUT_COLS;      // 16384

    size_t smem_bytes = (size_t)inter_dim * SLICE * sizeof(float)
                      + (size_t)NWARPS * 32 * sizeof(int2);   // 196608 + 4096
    cudaFuncSetAttribute(spmm_kernel,
                         cudaFuncAttributeMaxDynamicSharedMemorySize,
                         (int)smem_bytes);

    prep_kernel<<<(nnz + 255) / 256, 256>>>(bidx, aidx, vals, ftab, nnz, N);
    spmm_kernel<<<NSLICES * ROW_BLOCKS, BLOCK_THREADS, smem_bytes>>>(
        W, (float*)d_out, N, inter_dim);
}

// round 3
// speedup vs baseline: 1.2543x; 1.2543x over previous
#include <cuda_runtime.h>

#define OUT_COLS 256
#define SLICE 64
#define NSLICES (OUT_COLS / SLICE)
#define BLOCK_THREADS 1024
#define NWARPS (BLOCK_THREADS / 32)
#define ROW_BLOCKS 38   // 4 slices * 38 = 152 CTAs = one wave on GB300 (152 SMs)

// scratch (static __device__ globals: no allocations allowed)
__device__ int2 g_pairs[1 << 20];          // (col, val_bits) per nnz
__device__ int  g_row_off[(1 << 16) + 2];  // N+1 row segment offsets

__global__ void prep_kernel(const int* __restrict__ bidx,
                            const int* __restrict__ aidx,
                            const float* __restrict__ vals,
                            const int* __restrict__ ftab,
                            int nnz, int N) {
    int k = blockIdx.x * blockDim.x + threadIdx.x;
    if (k >= nnz) return;
    int col = ftab[aidx[k]];
    g_pairs[k] = make_int2(col, __float_as_int(vals[k]));
    int b = bidx[k];
    int prev = (k == 0) ? -1 : bidx[k - 1];
    for (int r = prev + 1; r <= b; ++r) g_row_off[r] = k;
    if (k == nnz - 1) {
        for (int r = b + 1; r <= N; ++r) g_row_off[r] = nnz;
    }
}

// Each CTA owns a 64-wide column slice of W in SMEM, stored so lane L holds
// columns (2L, 2L+1) as a float2 -> one LDS.64 per weight row per nnz.
__global__ __launch_bounds__(BLOCK_THREADS, 1)
void spmm_kernel(const float* __restrict__ W, float* __restrict__ out,
                 int N, int inter_dim) {
    extern __shared__ float smem[];
    float2* Ws2 = (float2*)smem;                        // [inter_dim][32] float2
    int2* stage = (int2*)(smem + inter_dim * SLICE);    // [NWARPS][32]

    int slice = blockIdx.x % NSLICES;
    int rb    = blockIdx.x / NSLICES;
    int nrb   = gridDim.x / NSLICES;

    int warp = threadIdx.x >> 5;
    int lane = threadIdx.x & 31;
    int2* mystage = stage + warp * 32;
    const int4* st4 = (const int4*)mystage;             // 2 pairs per int4

    int col0 = slice * SLICE;

    // Cooperative copy of the 64-col slice (contiguous, so float4 is fine;
    // float2 layout [r][32] is identical to a contiguous 64-float row copy).
    int nvec = inter_dim * (SLICE / 4);
    for (int i = threadIdx.x; i < nvec; i += BLOCK_THREADS) {
        int r  = i >> 4;
        int c4 = i & 15;
        float4 v = *(const float4*)(W + (size_t)r * OUT_COLS + col0 + c4 * 4);
        *(float4*)(smem + r * SLICE + c4 * 4) = v;
    }
    __syncthreads();

    for (int row = rb * NWARPS + warp; row < N; row += nrb * NWARPS) {
        int s = g_row_off[row];
        int e = g_row_off[row + 1];
        float2 accA = make_float2(0.f, 0.f);
        float2 accB = make_float2(0.f, 0.f);
        for (int base = s; base < e; base += 32) {
            int cnt = min(32, e - base);
            if (lane < cnt) mystage[lane] = g_pairs[base + lane];
            __syncwarp();
            int half = cnt >> 1;
#pragma unroll 4
            for (int j2 = 0; j2 < half; ++j2) {
                int4 q = st4[j2];                       // uniform LDS.128: 2 pairs
                float2 w0 = Ws2[q.x * 32 + lane];       // LDS.64, conflict-free
                accA.x = fmaf(__int_as_float(q.y), w0.x, accA.x);
                accA.y = fmaf(__int_as_float(q.y), w0.y, accA.y);
                float2 w1 = Ws2[q.z * 32 + lane];
                accB.x = fmaf(__int_as_float(q.w), w1.x, accB.x);
                accB.y = fmaf(__int_as_float(q.w), w1.y, accB.y);
            }
            if (cnt & 1) {
                int2 p = mystage[cnt - 1];
                float2 w = Ws2[p.x * 32 + lane];
                float v = __int_as_float(p.y);
                accA.x = fmaf(v, w.x, accA.x);
                accA.y = fmaf(v, w.y, accA.y);
            }
            __syncwarp();
        }
        float2 r2 = make_float2(accA.x + accB.x, accA.y + accB.y);
        *(float2*)(out + (size_t)row * OUT_COLS + col0 + 2 * lane) = r2;
    }
}

extern "C" void kernel_launch(void* const* d_in, const int* in_sizes, int n_in,
                              void* d_out, int out_size) {
    const int*   bidx = (const int*)d_in[0];
    const int*   aidx = (const int*)d_in[1];
    const float* vals = (const float*)d_in[2];
    const int*   ftab = (const int*)d_in[3];
    const float* W    = (const float*)d_in[4];

    int nnz       = in_sizes[0];
    int inter_dim = in_sizes[4] / OUT_COLS;   // 768
    int N         = out_size / OUT_COLS;      // 16384

    size_t smem_bytes = (size_t)inter_dim * SLICE * sizeof(float)
                      + (size_t)NWARPS * 32 * sizeof(int2);   // 196608 + 8192
    cudaFuncSetAttribute(spmm_kernel,
                         cudaFuncAttributeMaxDynamicSharedMemorySize,
                         (int)smem_bytes);

    prep_kernel<<<(nnz + 255) / 256, 256>>>(bidx, aidx, vals, ftab, nnz, N);
    spmm_kernel<<<NSLICES * ROW_BLOCKS, BLOCK_THREADS, smem_bytes>>>(
        W, (float*)d_out, N, inter_dim);
}

// round 5
// speedup vs baseline: 1.2628x; 1.0068x over previous
#include <cuda_runtime.h>

#define OUT_COLS 256
#define SLICE 64
#define NSLICES (OUT_COLS / SLICE)
#define BLOCK_THREADS 1024
#define NWARPS (BLOCK_THREADS / 32)
#define ROW_BLOCKS 38   // 4 slices * 38 = 152 CTAs = one wave on GB300 (152 SMs)

// scratch (static __device__ globals: no allocations allowed)
__device__ int2 g_pairs[1 << 20];          // (col, val_bits) per nnz
__device__ int  g_row_off[(1 << 16) + 2];  // N+1 row segment offsets

__global__ void prep_kernel(const int* __restrict__ bidx,
                            const int* __restrict__ aidx,
                            const float* __restrict__ vals,
                            const int* __restrict__ ftab,
                            int nnz, int N) {
    int k = blockIdx.x * blockDim.x + threadIdx.x;
    if (k >= nnz) return;
    int col = ftab[aidx[k]];
    g_pairs[k] = make_int2(col, __float_as_int(vals[k]));
    int b = bidx[k];
    int prev = (k == 0) ? -1 : bidx[k - 1];
    for (int r = prev + 1; r <= b; ++r) g_row_off[r] = k;
    if (k == nnz - 1) {
        for (int r = b + 1; r <= N; ++r) g_row_off[r] = nnz;
    }
}

// Each CTA owns a 64-wide column slice of W in SMEM (lane L holds cols 2L,2L+1
// as float2). Each warp processes TWO rows concurrently: two independent
// LDS->FFMA chains per warp to hide the 29-cyc smem latency.
__global__ __launch_bounds__(BLOCK_THREADS, 1)
void spmm_kernel(const float* __restrict__ W, float* __restrict__ out,
                 int N, int inter_dim) {
    extern __shared__ float smem[];
    float2* Ws2 = (float2*)smem;                        // [inter_dim][32] float2
    int2* stage = (int2*)(smem + inter_dim * SLICE);    // [NWARPS][64]

    int slice = blockIdx.x % NSLICES;
    int rb    = blockIdx.x / NSLICES;
    int nrb   = gridDim.x / NSLICES;

    int warp = threadIdx.x >> 5;
    int lane = threadIdx.x & 31;
    int2* st = stage + warp * 64;
    const int4* stA = (const int4*)st;                  // row0 pairs, 2 per int4
    const int4* stB = (const int4*)(st + 32);           // row1 pairs

    int col0 = slice * SLICE;

    // Cooperative copy of the 64-col weight slice into SMEM.
    int nvec = inter_dim * (SLICE / 4);
    for (int i = threadIdx.x; i < nvec; i += BLOCK_THREADS) {
        int r  = i >> 4;
        int c4 = i & 15;
        float4 v = *(const float4*)(W + (size_t)r * OUT_COLS + col0 + c4 * 4);
        *(float4*)(smem + r * SLICE + c4 * 4) = v;
    }
    __syncthreads();

    int rowStride = nrb * NWARPS * 2;
    for (int row0 = (rb * NWARPS + warp) * 2; row0 < N; row0 += rowStride) {
        int row1 = row0 + 1;                            // N even: row1 < N
        int s0 = g_row_off[row0], e0 = g_row_off[row0 + 1];
        int s1 = g_row_off[row1], e1 = g_row_off[row1 + 1];
        float2 acc0 = make_float2(0.f, 0.f);
        float2 acc1 = make_float2(0.f, 0.f);

        while (s0 < e0 || s1 < e1) {
            int cnt0 = min(32, e0 - s0);
            int cnt1 = min(32, e1 - s1);
            if (lane < cnt0) st[lane]      = g_pairs[s0 + lane];
            if (lane < cnt1) st[32 + lane] = g_pairs[s1 + lane];
            __syncwarp();
            int h0 = cnt0 >> 1, h1 = cnt1 >> 1;
            int joint = min(h0, h1);
#pragma unroll 2
            for (int j = 0; j < joint; ++j) {           // two independent chains
                int4 q0 = stA[j];
                int4 q1 = stB[j];
                float2 wa = Ws2[q0.x * 32 + lane];
                float2 wb = Ws2[q1.x * 32 + lane];
                acc0.x = fmaf(__int_as_float(q0.y), wa.x, acc0.x);
                acc0.y = fmaf(__int_as_float(q0.y), wa.y, acc0.y);
                acc1.x = fmaf(__int_as_float(q1.y), wb.x, acc1.x);
                acc1.y = fmaf(__int_as_float(q1.y), wb.y, acc1.y);
                float2 wc = Ws2[q0.z * 32 + lane];
                float2 wd = Ws2[q1.z * 32 + lane];
                acc0.x = fmaf(__int_as_float(q0.w), wc.x, acc0.x);
                acc0.y = fmaf(__int_as_float(q0.w), wc.y, acc0.y);
                acc1.x = fmaf(__int_as_float(q1.w), wd.x, acc1.x);
                acc1.y = fmaf(__int_as_float(q1.w), wd.y, acc1.y);
            }
            for (int j = joint; j < h0; ++j) {          // row0 leftover pairs
                int4 q = stA[j];
                float2 wa = Ws2[q.x * 32 + lane];
                acc0.x = fmaf(__int_as_float(q.y), wa.x, acc0.x);
                acc0.y = fmaf(__int_as_float(q.y), wa.y, acc0.y);
                float2 wc = Ws2[q.z * 32 + lane];
                acc0.x = fmaf(__int_as_float(q.w), wc.x, acc0.x);
                acc0.y = fmaf(__int_as_float(q.w), wc.y, acc0.y);
            }
            if (cnt0 & 1) {
                int2 p = st[cnt0 - 1];
                float2 w = Ws2[p.x * 32 + lane];
                float v = __int_as_float(p.y);
                acc0.x = fmaf(v, w.x, acc0.x);
                acc0.y = fmaf(v, w.y, acc0.y);
            }
            for (int j = joint; j < h1; ++j) {          // row1 leftover pairs
                int4 q = stB[j];
                float2 wb = Ws2[q.x * 32 + lane];
                acc1.x = fmaf(__int_as_float(q.y), wb.x, acc1.x);
                acc1.y = fmaf(__int_as_float(q.y), wb.y, acc1.y);
                float2 wd = Ws2[q.z * 32 + lane];
                acc1.x = fmaf(__int_as_float(q.w), wd.x, acc1.x);
                acc1.y = fmaf(__int_as_float(q.w), wd.y, acc1.y);
            }
            if (cnt1 & 1) {
                int2 p = st[32 + cnt1 - 1];
                float2 w = Ws2[p.x * 32 + lane];
                float v = __int_as_float(p.y);
                acc1.x = fmaf(v, w.x, acc1.x);
                acc1.y = fmaf(v, w.y, acc1.y);
            }
            __syncwarp();
            s0 += cnt0; s1 += cnt1;
        }
        *(float2*)(out + (size_t)row0 * OUT_COLS + col0 + 2 * lane) = acc0;
        *(float2*)(out + (size_t)row1 * OUT_COLS + col0 + 2 * lane) = acc1;
    }
}

extern "C" void kernel_launch(void* const* d_in, const int* in_sizes, int n_in,
                              void* d_out, int out_size) {
    const int*   bidx = (const int*)d_in[0];
    const int*   aidx = (const int*)d_in[1];
    const float* vals = (const float*)d_in[2];
    const int*   ftab = (const int*)d_in[3];
    const float* W    = (const float*)d_in[4];

    int nnz       = in_sizes[0];
    int inter_dim = in_sizes[4] / OUT_COLS;   // 768
    int N         = out_size / OUT_COLS;      // 16384

    size_t smem_bytes = (size_t)inter_dim * SLICE * sizeof(float)
                      + (size_t)NWARPS * 64 * sizeof(int2);   // 196608 + 16384
    cudaFuncSetAttribute(spmm_kernel,
                         cudaFuncAttributeMaxDynamicSharedMemorySize,
                         (int)smem_bytes);

    prep_kernel<<<(nnz + 255) / 256, 256>>>(bidx, aidx, vals, ftab, nnz, N);
    spmm_kernel<<<NSLICES * ROW_BLOCKS, BLOCK_THREADS, smem_bytes>>>(
        W, (float*)d_out, N, inter_dim);
}

// round 10
// speedup vs baseline: 1.5206x; 1.2041x over previous
#include <cuda_runtime.h>
#include <cuda_fp16.h>

#define OUT_COLS 256
#define SLICE 128
#define NSLICES (OUT_COLS / SLICE)          // 2
#define BLOCK_THREADS 1024
#define NWARPS (BLOCK_THREADS / 32)
#define ROW_BLOCKS 76                       // 2 slices * 76 = 152 CTAs = 1 wave

typedef unsigned long long ull;

// scratch (static __device__ globals: no allocations allowed)
__device__ int2   g_pairs[1 << 20];          // (col, val_bits) per nnz
__device__ int    g_row_off[(1 << 16) + 2];  // N+1 row segment offsets
__device__ __half g_whalf[1 << 18];          // fp16 copy of W (768*256 fits)

__global__ void prep_kernel(const int* __restrict__ bidx,
                            const int* __restrict__ aidx,
                            const float* __restrict__ vals,
                            const int* __restrict__ ftab,
                            int nnz, int N) {
    int k = blockIdx.x * blockDim.x + threadIdx.x;
    if (k >= nnz) return;
    int col = ftab[aidx[k]];
    g_pairs[k] = make_int2(col, __float_as_int(vals[k]));
    int b = bidx[k];
    int prev = (k == 0) ? -1 : bidx[k - 1];
    for (int r = prev + 1; r <= b; ++r) g_row_off[r] = k;
    if (k == nnz - 1) {
        for (int r = b + 1; r <= N; ++r) g_row_off[r] = nnz;
    }
}

__global__ void convert_w_kernel(const float* __restrict__ W, int n) {
    int k = blockIdx.x * blockDim.x + threadIdx.x;   // half2 index
    if (2 * k + 1 < n) {
        float2 f = *(const float2*)(W + 2 * k);
        ((__half2*)g_whalf)[k] = __float22half2_rn(f);
    }
}

// One nnz: read 4 fp16 weight cols (one LDS.64), fp32-accumulate via packed
// fma.rn.f32x2 into two f32x2 accumulators.
__device__ __forceinline__ void accum1(int col, int vbits, const char* Wsl,
                                       ull& a0, ull& a1) {
    uint2 u = *(const uint2*)(Wsl + col * (SLICE * 2));
    float2 f0 = __half22float2(*(__half2*)&u.x);
    float2 f1 = __half22float2(*(__half2*)&u.y);
    ull vv;
    asm("mov.b64 %0, {%1, %1};" : "=l"(vv) : "r"(vbits));
    asm("fma.rn.f32x2 %0, %1, %2, %0;" : "+l"(a0)
        : "l"(vv), "l"(*(ull*)&f0));
    asm("fma.rn.f32x2 %0, %1, %2, %0;" : "+l"(a1)
        : "l"(vv), "l"(*(ull*)&f1));
}

// Each CTA owns a 128-wide fp16 weight slice in SMEM. Each warp processes two
// rows concurrently (two independent LDS->cvt->FFMA2 chains).
__global__ __launch_bounds__(BLOCK_THREADS, 1)
void spmm_kernel(float* __restrict__ out, int N, int inter_dim) {
    extern __shared__ char smem[];
    char* Ws = smem;                                   // [inter_dim][128] half
    int2* stage = (int2*)(smem + inter_dim * SLICE * 2);  // [NWARPS][64]

    int slice = blockIdx.x % NSLICES;
    int rb    = blockIdx.x / NSLICES;
    int nrb   = gridDim.x / NSLICES;

    int warp = threadIdx.x >> 5;
    int lane = threadIdx.x & 31;
    int2* st = stage + warp * 64;
    const int4* stA = (const int4*)st;
    const int4* stB = (const int4*)(st + 32);
    const char* Wsl = Ws + lane * 8;                   // this lane's 4 cols

    int col0 = slice * SLICE;

    // Fill weight slice: 16 uint4 per row (128 halfs = 256 B).
    {
        const uint4* Wh4 = (const uint4*)g_whalf;      // 8 halfs per uint4
        int rowv = OUT_COLS / 8;                       // 32 uint4 per full row
        int base = col0 / 8;
        int nvec = inter_dim * (SLICE / 8);            // 12288
        for (int i = threadIdx.x; i < nvec; i += BLOCK_THREADS) {
            int r = i >> 4;
            int c = i & 15;
            ((uint4*)Ws)[r * 16 + c] = Wh4[r * rowv + base + c];
        }
    }
    __syncthreads();

    int rowStride = nrb * NWARPS * 2;
    for (int row0 = (rb * NWARPS + warp) * 2; row0 < N; row0 += rowStride) {
        int row1 = row0 + 1;                            // N even
        int s0 = g_row_off[row0], e0 = g_row_off[row0 + 1];
        int s1 = g_row_off[row1], e1 = g_row_off[row1 + 1];
        ull a00 = 0, a01 = 0;                           // row0: cols 4L..4L+3
        ull a10 = 0, a11 = 0;                           // row1

        while (s0 < e0 || s1 < e1) {
            int cnt0 = min(32, e0 - s0);
            int cnt1 = min(32, e1 - s1);
            if (lane < cnt0) st[lane]      = g_pairs[s0 + lane];
            if (lane < cnt1) st[32 + lane] = g_pairs[s1 + lane];
            __syncwarp();
            int h0 = cnt0 >> 1, h1 = cnt1 >> 1;
            int joint = min(h0, h1);
#pragma unroll 2
            for (int j = 0; j < joint; ++j) {
                int4 q0 = stA[j];
                int4 q1 = stB[j];
                accum1(q0.x, q0.y, Wsl, a00, a01);
                accum1(q1.x, q1.y, Wsl, a10, a11);
                accum1(q0.z, q0.w, Wsl, a00, a01);
                accum1(q1.z, q1.w, Wsl, a10, a11);
            }
            for (int j = joint; j < h0; ++j) {
                int4 q = stA[j];
                accum1(q.x, q.y, Wsl, a00, a01);
                accum1(q.z, q.w, Wsl, a00, a01);
            }
            if (cnt0 & 1) {
                int2 p = st[cnt0 - 1];
                accum1(p.x, p.y, Wsl, a00, a01);
            }
            for (int j = joint; j < h1; ++j) {
                int4 q = stB[j];
                accum1(q.x, q.y, Wsl, a10, a11);
                accum1(q.z, q.w, Wsl, a10, a11);
            }
            if (cnt1 & 1) {
                int2 p = st[32 + cnt1 - 1];
                accum1(p.x, p.y, Wsl, a10, a11);
            }
            __syncwarp();
            s0 += cnt0; s1 += cnt1;
        }
        float2 lo, hi;
        lo = *(float2*)&a00; hi = *(float2*)&a01;
        *(float4*)(out + (size_t)row0 * OUT_COLS + col0 + 4 * lane)
            = make_float4(lo.x, lo.y, hi.x, hi.y);
        lo = *(float2*)&a10; hi = *(float2*)&a11;
        *(float4*)(out + (size_t)row1 * OUT_COLS + col0 + 4 * lane)
            = make_float4(lo.x, lo.y, hi.x, hi.y);
    }
}

extern "C" void kernel_launch(void* const* d_in, const int* in_sizes, int n_in,
                              void* d_out, int out_size) {
    const int*   bidx = (const int*)d_in[0];
    const int*   aidx = (const int*)d_in[1];
    const float* vals = (const float*)d_in[2];
    const int*   ftab = (const int*)d_in[3];
    const float* W    = (const float*)d_in[4];

    int nnz       = in_sizes[0];
    int wn        = in_sizes[4];              // 768*256
    int inter_dim = wn / OUT_COLS;            // 768
    int N         = out_size / OUT_COLS;      // 16384

    size_t smem_bytes = (size_t)inter_dim * SLICE * 2
                      + (size_t)NWARPS * 64 * sizeof(int2);   // 196608 + 16384
    cudaFuncSetAttribute(spmm_kernel,
                         cudaFuncAttributeMaxDynamicSharedMemorySize,
                         (int)smem_bytes);

    prep_kernel<<<(nnz + 255) / 256, 256>>>(bidx, aidx, vals, ftab, nnz, N);
    convert_w_kernel<<<(wn / 2 + 255) / 256, 256>>>(W, wn);
    spmm_kernel<<<NSLICES * ROW_BLOCKS, BLOCK_THREADS, smem_bytes>>>(
        (float*)d_out, N, inter_dim);
}